// round 16
// baseline (speedup 1.0000x reference)
#include <cuda_runtime.h>
#include <cuda_bf16.h>
#include <cstdint>

#define B_    8
#define L_    768
#define H_    16
#define DK_   64
#define D_    1024
#define BH_   128
#define M_    6144
#define SCALE 0.125f

// Scratch (device globals; allocation forbidden)
__device__ float g_Xr[3][M_ * D_];                     // tf32 inputs, k-permuted
__device__ float g_Wq[D_ * D_], g_Wk[D_ * D_], g_Wv[D_ * D_], g_Wo[D_ * D_];
__device__ float g_Qp[BH_ * L_ * DK_];                 // [bh][l][dk] tf32
__device__ float g_Kp[BH_ * L_ * DK_];                 // tf32
__device__ float g_Vt[BH_ * DK_ * L_];                 // V^T [bh][dk][l] tf32
__device__ __nv_bfloat16 g_Ec[1535 * 64];              // bf16 rel embedding
__device__ float g_O2[(size_t)M_ * D_];                // attn out, merged, tf32, D-permuted

__device__ __forceinline__ float to_tf32(float x) {
    float r;
    asm("cvt.rna.tf32.f32 %0, %1;" : "=f"(r) : "f"(x));
    return r;
}
__device__ __forceinline__ uint32_t pack_bf16(float lo, float hi) {
    uint32_t r;
    asm("cvt.rn.bf16x2.f32 %0, %1, %2;" : "=r"(r) : "f"(hi), "f"(lo));
    return r;
}
__device__ __forceinline__ uint32_t smem_u32(const void* p) {
    uint32_t a;
    asm("{ .reg .u64 t; cvta.to.shared.u64 t, %1; cvt.u32.u64 %0, t; }"
        : "=r"(a) : "l"(p));
    return a;
}
__device__ __forceinline__ void mma_tf32(float* d, const uint32_t* a, const uint32_t* b) {
    asm volatile(
        "mma.sync.aligned.m16n8k8.row.col.f32.tf32.tf32.f32 "
        "{%0,%1,%2,%3}, {%4,%5,%6,%7}, {%8,%9}, {%0,%1,%2,%3};"
        : "+f"(d[0]), "+f"(d[1]), "+f"(d[2]), "+f"(d[3])
        : "r"(a[0]), "r"(a[1]), "r"(a[2]), "r"(a[3]), "r"(b[0]), "r"(b[1]));
}
__device__ __forceinline__ void mma_bf16(float* d, const uint32_t* a, const uint32_t* b) {
    asm volatile(
        "mma.sync.aligned.m16n8k16.row.col.f32.bf16.bf16.f32 "
        "{%0,%1,%2,%3}, {%4,%5,%6,%7}, {%8,%9}, {%0,%1,%2,%3};"
        : "+f"(d[0]), "+f"(d[1]), "+f"(d[2]), "+f"(d[3])
        : "r"(a[0]), "r"(a[1]), "r"(a[2]), "r"(a[3]), "r"(b[0]), "r"(b[1]));
}
#define CP_A16(dst, src) \
    asm volatile("cp.async.ca.shared.global [%0], [%1], 16;" :: "r"(dst), "l"(src) : "memory")
#define CP_A16Z(dst, src, sz) \
    asm volatile("cp.async.ca.shared.global [%0], [%1], 16, %2;" :: "r"(dst), "l"(src), "r"(sz) : "memory")
#define CP_COMMIT() asm volatile("cp.async.commit_group;" ::: "memory")
#define CP_WAIT2()  asm volatile("cp.async.wait_group 2;" ::: "memory")
#define CP_WAIT1()  asm volatile("cp.async.wait_group 1;" ::: "memory")
#define CP_WAIT0()  asm volatile("cp.async.wait_group 0;" ::: "memory")

// ---------------------------------------------------------------------------
// Unified conversion kernel, z in [0,7]:
//   z 0-3: weights w_q,w_k,w_v,w_o -> tf32 + within-8 k-permutation
//   z 4  : relE -> bf16
//   z 5-7: inputs query,key,value -> tf32 + k-permutation into g_Xr[z-5]
// ---------------------------------------------------------------------------
__global__ __launch_bounds__(256)
void conv_all(const float4* __restrict__ wq_in, const float4* __restrict__ wk_in,
              const float4* __restrict__ wv_in, const float4* __restrict__ wo_in,
              const float4* __restrict__ e_in,
              const float4* __restrict__ xq_in, const float4* __restrict__ xk_in,
              const float4* __restrict__ xv_in,
              int n4w, int n4e, int n4x)
{
    const int z = blockIdx.z;
    int i = blockIdx.x * 256 + threadIdx.x;
    if (z == 4) {
        if (i < n4e) {
            float4 v = e_in[i];
            __nv_bfloat16* o = g_Ec + i * 4;
            o[0] = __float2bfloat16(v.x);
            o[1] = __float2bfloat16(v.y);
            o[2] = __float2bfloat16(v.z);
            o[3] = __float2bfloat16(v.w);
        }
        return;
    }
    const float4* in;
    float* out;
    int n4;
    if (z < 4) {
        in  = (z == 0) ? wq_in : (z == 1) ? wk_in : (z == 2) ? wv_in : wo_in;
        out = (z == 0) ? g_Wq  : (z == 1) ? g_Wk  : (z == 2) ? g_Wv  : g_Wo;
        n4  = n4w;
    } else {
        in  = (z == 5) ? xq_in : (z == 6) ? xk_in : xv_in;
        out = g_Xr[z - 5];
        n4  = n4x;
    }
    if (i < n4) {
        float4 v = in[i];
        const int base = (i >> 1) * 8 + (i & 1);
        out[base + 0] = to_tf32(v.x);
        out[base + 2] = to_tf32(v.y);
        out[base + 4] = to_tf32(v.z);
        out[base + 6] = to_tf32(v.w);
    }
}

// ---------------------------------------------------------------------------
// QKV projection (R12/14-proven). k-permuted, LDS.64 frags, stride-40.
// ---------------------------------------------------------------------------
__global__ __launch_bounds__(256)
void proj_qkv(const float* __restrict__ bq, const float* __restrict__ bk,
              const float* __restrict__ bv, float* __restrict__ Qout,
              float* __restrict__ Kout)
{
    extern __shared__ float sm[];
    const uint32_t smb = smem_u32(sm);
    constexpr int STG = 2 * 128 * 40;

    const int tid = threadIdx.x, lane = tid & 31, wid = tid >> 5;
    const int g4 = lane >> 2, cq = lane & 3;
    const int wm = (wid & 1) * 64, wn = (wid >> 1) * 32;
    const int z = blockIdx.z;

    const float* Ag = g_Xr[z];
    const float* Bg = (z == 0) ? g_Wq : (z == 1) ? g_Wk : g_Wv;
    const float* bias = (z == 0) ? bq : (z == 1) ? bk : bv;

    const float* Arow = Ag + (size_t)(blockIdx.y * 128) * 1024;
    const float* Brow = Bg + (size_t)(blockIdx.x * 128) * 1024;

    auto loadAB = [&](int t, int s) {
        const uint32_t base = smb + (uint32_t)s * STG * 4;
        const int k0 = t * 32;
#pragma unroll
        for (int i = 0; i < 4; ++i) {
            int idx = tid + i * 256;
            int r = idx >> 3, seg = idx & 7;
            CP_A16(base + (uint32_t)(r * 40 + seg * 4) * 4,
                   Arow + (size_t)r * 1024 + k0 + seg * 4);
        }
#pragma unroll
        for (int i = 0; i < 4; ++i) {
            int idx = tid + i * 256;
            int r = idx >> 3, seg = idx & 7;
            CP_A16(base + (uint32_t)(128 * 40 + r * 40 + seg * 4) * 4,
                   Brow + (size_t)r * 1024 + k0 + seg * 4);
        }
    };

    float acc[4][4][4] = {};

    loadAB(0, 0); CP_COMMIT();

    for (int t = 0; t < 32; ++t) {
        if (t + 1 < 32) { loadAB(t + 1, (t + 1) & 1); CP_COMMIT(); }
        if (t + 1 < 32) { CP_WAIT1(); } else { CP_WAIT0(); }
        __syncthreads();

        const float* As = sm + (t & 1) * STG;
        const float* Bs = As + 128 * 40;
#pragma unroll
        for (int ks = 0; ks < 4; ++ks) {
            uint32_t afr[4][4], bfr[4][2];
#pragma unroll
            for (int m = 0; m < 4; ++m) {
                const float* p = As + (wm + m * 16 + g4) * 40 + ks * 8 + 2 * cq;
                float2 lo = *(const float2*)p;
                float2 hi = *(const float2*)(p + 8 * 40);
                afr[m][0] = __float_as_uint(lo.x);
                afr[m][1] = __float_as_uint(hi.x);
                afr[m][2] = __float_as_uint(lo.y);
                afr[m][3] = __float_as_uint(hi.y);
            }
#pragma unroll
            for (int n = 0; n < 4; ++n) {
                const float* p = Bs + (wn + n * 8 + g4) * 40 + ks * 8 + 2 * cq;
                float2 b = *(const float2*)p;
                bfr[n][0] = __float_as_uint(b.x);
                bfr[n][1] = __float_as_uint(b.y);
            }
#pragma unroll
            for (int m = 0; m < 4; ++m)
#pragma unroll
                for (int n = 0; n < 4; ++n)
                    mma_tf32(acc[m][n], afr[m], bfr[n]);
        }
        __syncthreads();
    }

    float* OUT = (z == 0) ? Qout : Kout;
#pragma unroll
    for (int m = 0; m < 4; ++m) {
#pragma unroll
        for (int n = 0; n < 4; ++n) {
            const int col = wn + n * 8 + cq * 2;
#pragma unroll
            for (int h2 = 0; h2 < 2; ++h2) {
                const int row = wm + m * 16 + g4 + h2 * 8;
                const float c0 = acc[m][n][h2 * 2 + 0];
                const float c1 = acc[m][n][h2 * 2 + 1];
                const int mg = blockIdx.y * 128 + row;
                const int ng = blockIdx.x * 128 + col;
                const int bb = mg / 768, l = mg - bb * 768;
                const int hh = ng >> 6, dd = ng & 63;
                if (z < 2) {
                    float* dst = OUT + (((size_t)(bb * 16 + hh) * 768) + l) * 64 + dd;
                    dst[0] = to_tf32(c0 + bias[ng]);
                    dst[1] = to_tf32(c1 + bias[ng + 1]);
                } else {
                    g_Vt[((size_t)(bb * 16 + hh) * 64 + dd    ) * 768 + l] = to_tf32(c0 + bias[ng]);
                    g_Vt[((size_t)(bb * 16 + hh) * 64 + dd + 1) * 768 + l] = to_tf32(c1 + bias[ng + 1]);
                }
            }
        }
    }
}

// ---------------------------------------------------------------------------
// Output projection (proven).
// ---------------------------------------------------------------------------
__global__ __launch_bounds__(256)
void proj_out(const float* __restrict__ bias, float* __restrict__ OUT)
{
    extern __shared__ float sm[];
    const uint32_t smb = smem_u32(sm);
    constexpr int STG = 2 * 128 * 40;

    const int tid = threadIdx.x, lane = tid & 31, wid = tid >> 5;
    const int g4 = lane >> 2, cq = lane & 3;
    const int wm = (wid & 1) * 64, wn = (wid >> 1) * 32;

    const float* Arow = g_O2 + (size_t)(blockIdx.y * 128) * 1024;
    const float* Brow = g_Wo + (size_t)(blockIdx.x * 128) * 1024;

    auto loadAB = [&](int t, int s) {
        const uint32_t base = smb + (uint32_t)s * STG * 4;
        const int k0 = t * 32;
#pragma unroll
        for (int i = 0; i < 4; ++i) {
            int idx = tid + i * 256;
            int r = idx >> 3, seg = idx & 7;
            CP_A16(base + (uint32_t)(r * 40 + seg * 4) * 4,
                   Arow + (size_t)r * 1024 + k0 + seg * 4);
        }
#pragma unroll
        for (int i = 0; i < 4; ++i) {
            int idx = tid + i * 256;
            int r = idx >> 3, seg = idx & 7;
            CP_A16(base + (uint32_t)(128 * 40 + r * 40 + seg * 4) * 4,
                   Brow + (size_t)r * 1024 + k0 + seg * 4);
        }
    };

    float acc[4][4][4] = {};

    loadAB(0, 0); CP_COMMIT();

    for (int t = 0; t < 32; ++t) {
        if (t + 1 < 32) { loadAB(t + 1, (t + 1) & 1); CP_COMMIT(); }
        if (t + 1 < 32) { CP_WAIT1(); } else { CP_WAIT0(); }
        __syncthreads();

        const float* As = sm + (t & 1) * STG;
        const float* Bs = As + 128 * 40;
#pragma unroll
        for (int ks = 0; ks < 4; ++ks) {
            uint32_t afr[4][4], bfr[4][2];
#pragma unroll
            for (int m = 0; m < 4; ++m) {
                const float* p = As + (wm + m * 16 + g4) * 40 + ks * 8 + 2 * cq;
                float2 lo = *(const float2*)p;
                float2 hi = *(const float2*)(p + 8 * 40);
                afr[m][0] = __float_as_uint(lo.x);
                afr[m][1] = __float_as_uint(hi.x);
                afr[m][2] = __float_as_uint(lo.y);
                afr[m][3] = __float_as_uint(hi.y);
            }
#pragma unroll
            for (int n = 0; n < 4; ++n) {
                const float* p = Bs + (wn + n * 8 + g4) * 40 + ks * 8 + 2 * cq;
                float2 b = *(const float2*)p;
                bfr[n][0] = __float_as_uint(b.x);
                bfr[n][1] = __float_as_uint(b.y);
            }
#pragma unroll
            for (int m = 0; m < 4; ++m)
#pragma unroll
                for (int n = 0; n < 4; ++n)
                    mma_tf32(acc[m][n], afr[m], bfr[n]);
        }
        __syncthreads();
    }

#pragma unroll
    for (int m = 0; m < 4; ++m) {
#pragma unroll
        for (int n = 0; n < 4; ++n) {
            const int col = wn + n * 8 + cq * 2;
#pragma unroll
            for (int h2 = 0; h2 < 2; ++h2) {
                const int row = wm + m * 16 + g4 + h2 * 8;
                const int mg = blockIdx.y * 128 + row;
                const int ng = blockIdx.x * 128 + col;
                float* dst = OUT + (size_t)mg * 1024 + ng;
                dst[0] = acc[m][n][h2 * 2 + 0] + bias[ng];
                dst[1] = acc[m][n][h2 * 2 + 1] + bias[ng + 1];
            }
        }
    }
}

// ---------------------------------------------------------------------------
// FULLY FUSED scores + rel + exp + AV (R14-proven). One CTA per (qt, bh).
// tf32 content scores, bf16 window scores, tf32 AV.
// ---------------------------------------------------------------------------
__global__ __launch_bounds__(256)
void scores_av()
{
    extern __shared__ float sm[];
    constexpr int BB_F = 128 * 68;
    constexpr int E_ELEM = 128 * 72;
    constexpr int W_ELEM = 128 * 136;
    float* Bbuf = sm;
    __nv_bfloat16* Ebuf = (__nv_bfloat16*)(sm + 2 * BB_F);
    __nv_bfloat16* Wbuf = Ebuf + 2 * E_ELEM;
    float* Vbuf = (float*)(Wbuf + 2 * W_ELEM);     // [64][132]
    float* Qstage = (float*)Wbuf;
    const uint32_t bb_a = smem_u32(Bbuf);
    const uint32_t eb_a = smem_u32(Ebuf);
    const uint32_t vb_a = smem_u32(Vbuf);
    const uint32_t wq_a = smem_u32(Qstage);

    const int tid  = threadIdx.x;
    const int lane = tid & 31, wid = tid >> 5;
    const int g4 = lane >> 2, cq = lane & 3;
    const int wm = wid * 16;
    const int qt = blockIdx.x, bh = blockIdx.y;

    const float* Qg = g_Qp + ((size_t)bh * 768 + qt * 128) * 64;
    const float* Kg = g_Kp + (size_t)bh * 768 * 64;
    const float* Vg = g_Vt + (size_t)bh * 64 * 768;
    const int base0 = 640 - qt * 128;

#pragma unroll
    for (int i = 0; i < 8; ++i) {
        int idx = tid + i * 256;
        int r = idx >> 4, seg = idx & 15;
        CP_A16(wq_a + (uint32_t)(r * 68 + seg * 4) * 4, Qg + r * 64 + seg * 4);
    }
    CP_COMMIT();

    auto loadTile = [&](int i) {
        const bool content = (i >= 2) && ((i & 1) == 0);
        if (content) {
            const int xt = (i - 2) >> 1;
            const uint32_t base = bb_a + (uint32_t)(xt & 1) * (BB_F * 4);
            const float* s0 = Kg + (size_t)xt * 128 * 64;
#pragma unroll
            for (int k = 0; k < 8; ++k) {
                int idx = tid + k * 256;
                int r = idx >> 4, seg = idx & 15;
                CP_A16(base + (uint32_t)(r * 68 + seg * 4) * 4, s0 + r * 64 + seg * 4);
            }
#pragma unroll
            for (int k = 0; k < 8; ++k) {
                int idx = tid + k * 256;
                int r = idx >> 5, seg = idx & 31;
                CP_A16(vb_a + (uint32_t)(r * 132 + seg * 4) * 4,
                       Vg + (size_t)r * 768 + xt * 128 + seg * 4);
            }
        } else {
            const int w = (i < 2) ? i : ((i + 1) >> 1);
            const uint32_t base = eb_a + (uint32_t)(w & 1) * (E_ELEM * 2);
            const int jb = base0 + w * 128;
#pragma unroll
            for (int k = 0; k < 4; ++k) {
                int idx = tid + k * 256;
                int r = idx >> 3, seg = idx & 7;
                int j = jb + r;
                int jc = (j > 1534) ? 1534 : j;
                unsigned sz = (j <= 1534) ? 16u : 0u;
                CP_A16Z(base + (uint32_t)(r * 72 + seg * 8) * 2,
                        g_Ec + (size_t)jc * 64 + seg * 8, sz);
            }
        }
    };

    loadTile(0); CP_COMMIT();
    loadTile(1); CP_COMMIT();

    CP_WAIT2();
    __syncthreads();

    uint32_t afr[8][4];
#pragma unroll
    for (int ks = 0; ks < 8; ++ks) {
        const float* q = Qstage + (wm + g4) * 68 + ks * 8 + cq;
        afr[ks][0] = __float_as_uint(q[0]);
        afr[ks][1] = __float_as_uint(q[8 * 68]);
        afr[ks][2] = __float_as_uint(q[4]);
        afr[ks][3] = __float_as_uint(q[8 * 68 + 4]);
    }
    uint32_t aqb[4][4];
#pragma unroll
    for (int ks = 0; ks < 4; ++ks) {
        const int row = wm + g4;
        const float* q0 = Qstage + row * 68 + ks * 16;
        const float* q1 = Qstage + (row + 8) * 68 + ks * 16;
        float2 x0 = *(const float2*)(q0 + 2 * cq);
        float2 x1 = *(const float2*)(q0 + 2 * cq + 8);
        float2 y0 = *(const float2*)(q1 + 2 * cq);
        float2 y1 = *(const float2*)(q1 + 2 * cq + 8);
        aqb[ks][0] = pack_bf16(x0.x, x0.y);
        aqb[ks][1] = pack_bf16(y0.x, y0.y);
        aqb[ks][2] = pack_bf16(x1.x, x1.y);
        aqb[ks][3] = pack_bf16(y1.x, y1.y);
    }
    __syncthreads();

    CP_WAIT1();
    __syncthreads();

    float o_acc[8][4] = {};
    float rs0 = 0.f, rs1 = 0.f;

    const int srcLo = (lane & ~3) | (cq >> 1);
    const int srcHi = (lane & ~3) | (2 + (cq >> 1));
    const bool oddq = (cq & 1);

#pragma unroll 1
    for (int i = 0; i < 13; ++i) {
        const bool content = (i >= 2) && ((i & 1) == 0);

        if (!content) {
            const int w = (i < 2) ? i : ((i + 1) >> 1);
            const uint32_t* Eb = (const uint32_t*)(Ebuf + (w & 1) * E_ELEM);
            float acc[16][4] = {};
#pragma unroll
            for (int ks = 0; ks < 4; ++ks) {
#pragma unroll
                for (int nt = 0; nt < 16; ++nt) {
                    const uint32_t* e = Eb + (nt * 8 + g4) * 36 + ks * 8 + cq;
                    uint32_t bfr[2] = { e[0], e[4] };
                    mma_bf16(acc[nt], aqb[ks], bfr);
                }
            }
            __nv_bfloat16* Wd = Wbuf + (w & 1) * W_ELEM;
#pragma unroll
            for (int nt = 0; nt < 16; ++nt) {
                const int col = nt * 8 + 2 * cq;
                *(uint32_t*)((char*)Wd + (size_t)((wm + g4) * 136 + col) * 2) =
                    pack_bf16(acc[nt][0], acc[nt][1]);
                *(uint32_t*)((char*)Wd + (size_t)((wm + g4 + 8) * 136 + col) * 2) =
                    pack_bf16(acc[nt][2], acc[nt][3]);
            }
        } else {
            const int xt = (i - 2) >> 1;
            const float* Bsb = Bbuf + (xt & 1) * BB_F;
            float acc[16][4] = {};
#pragma unroll
            for (int ks = 0; ks < 8; ++ks) {
#pragma unroll
                for (int nt = 0; nt < 16; ++nt) {
                    const float* b = Bsb + (nt * 8 + g4) * 68 + ks * 8 + cq;
                    uint32_t bfr[2] = { __float_as_uint(b[0]), __float_as_uint(b[4]) };
                    mma_tf32(acc[nt], afr[ks], bfr);
                }
            }
            const __nv_bfloat16* W0 = Wbuf + (xt & 1) * W_ELEM;
            const __nv_bfloat16* W1 = Wbuf + ((xt + 1) & 1) * W_ELEM;
            const int r0i = wm + g4, r1i = wm + g4 + 8;
#pragma unroll
            for (int nt = 0; nt < 16; ++nt) {
                const int col = nt * 8 + 2 * cq;
                int c0 = col - r0i + 127, c1 = c0 + 1;
                float e0 = __bfloat162float((c0 < 128) ? W0[r0i * 136 + c0]
                                                       : W1[r0i * 136 + c0 - 128]);
                float e1 = __bfloat162float((c1 < 128) ? W0[r0i * 136 + c1]
                                                       : W1[r0i * 136 + c1 - 128]);
                int d0 = col - r1i + 127, d1 = d0 + 1;
                float f0 = __bfloat162float((d0 < 128) ? W0[r1i * 136 + d0]
                                                       : W1[r1i * 136 + d0 - 128]);
                float f1 = __bfloat162float((d1 < 128) ? W0[r1i * 136 + d1]
                                                       : W1[r1i * 136 + d1 - 128]);
                float p0 = __expf(SCALE * (acc[nt][0] + e0));
                float p1 = __expf(SCALE * (acc[nt][1] + e1));
                float p2 = __expf(SCALE * (acc[nt][2] + f0));
                float p3 = __expf(SCALE * (acc[nt][3] + f1));
                rs0 += p0 + p1;
                rs1 += p2 + p3;
                acc[nt][0] = to_tf32(p0);
                acc[nt][1] = to_tf32(p1);
                acc[nt][2] = to_tf32(p2);
                acc[nt][3] = to_tf32(p3);
            }
#pragma unroll
            for (int kk = 0; kk < 16; ++kk) {
                float x0 = __shfl_sync(0xffffffffu, acc[kk][0], srcLo);
                float x1 = __shfl_sync(0xffffffffu, acc[kk][1], srcLo);
                float y0 = __shfl_sync(0xffffffffu, acc[kk][0], srcHi);
                float y1 = __shfl_sync(0xffffffffu, acc[kk][1], srcHi);
                float z0 = __shfl_sync(0xffffffffu, acc[kk][2], srcLo);
                float z1 = __shfl_sync(0xffffffffu, acc[kk][3], srcLo);
                float u0 = __shfl_sync(0xffffffffu, acc[kk][2], srcHi);
                float u1 = __shfl_sync(0xffffffffu, acc[kk][3], srcHi);
                uint32_t a[4];
                a[0] = __float_as_uint(oddq ? x1 : x0);
                a[1] = __float_as_uint(oddq ? z1 : z0);
                a[2] = __float_as_uint(oddq ? y1 : y0);
                a[3] = __float_as_uint(oddq ? u1 : u0);
#pragma unroll
                for (int dt = 0; dt < 8; ++dt) {
                    const float* v = Vbuf + (dt * 8 + g4) * 132 + kk * 8 + cq;
                    uint32_t bfr[2] = { __float_as_uint(v[0]), __float_as_uint(v[4]) };
                    mma_tf32(o_acc[dt], a, bfr);
                }
            }
        }

        __syncthreads();
        if (i + 2 < 13) { loadTile(i + 2); CP_COMMIT(); }
        if (i + 1 < 13) {
            if (i + 2 < 13) { CP_WAIT1(); } else { CP_WAIT0(); }
            __syncthreads();
        }
    }

    rs0 += __shfl_xor_sync(0xffffffffu, rs0, 1);
    rs0 += __shfl_xor_sync(0xffffffffu, rs0, 2);
    rs1 += __shfl_xor_sync(0xffffffffu, rs1, 1);
    rs1 += __shfl_xor_sync(0xffffffffu, rs1, 2);
    const float inv0 = 1.0f / rs0, inv1 = 1.0f / rs1;

    const int b = bh >> 4, h = bh & 15;
    const int j0 = 2 * cq;
    const int pp0 = (j0 & 3) * 2 + (j0 >> 2);
    const int pp1 = ((j0 + 1) & 3) * 2 + ((j0 + 1) >> 2);
    const int q0r = qt * 128 + wm + g4;
    const int q1r = q0r + 8;
#pragma unroll
    for (int dt = 0; dt < 8; ++dt) {
        float* dst0 = g_O2 + ((size_t)(b * 768) + q0r) * 1024 + h * 64 + dt * 8;
        float* dst1 = g_O2 + ((size_t)(b * 768) + q1r) * 1024 + h * 64 + dt * 8;
        dst0[pp0] = to_tf32(o_acc[dt][0] * inv0);
        dst0[pp1] = to_tf32(o_acc[dt][1] * inv0);
        dst1[pp0] = to_tf32(o_acc[dt][2] * inv1);
        dst1[pp1] = to_tf32(o_acc[dt][3] * inv1);
    }
}

// ---------------------------------------------------------------------------
extern "C" void kernel_launch(void* const* d_in, const int* in_sizes, int n_in,
                              void* d_out, int out_size)
{
    const float* query = (const float*)d_in[0];
    const float* key   = (const float*)d_in[1];
    const float* value = (const float*)d_in[2];
    const float* w_q   = (const float*)d_in[3];
    const float* b_q   = (const float*)d_in[4];
    const float* w_k   = (const float*)d_in[5];
    const float* b_k   = (const float*)d_in[6];
    const float* w_v   = (const float*)d_in[7];
    const float* b_v   = (const float*)d_in[8];
    const float* w_o   = (const float*)d_in[9];
    const float* b_o   = (const float*)d_in[10];
    const float* relE  = (const float*)d_in[11];
    float* out = (float*)d_out;

    float *qp, *kp;
    cudaGetSymbolAddress((void**)&qp, g_Qp);
    cudaGetSymbolAddress((void**)&kp, g_Kp);

    const int SMEMP   = 2 * 2 * 128 * 40 * 4;                    // 81920
    const int SC_SMEM = 2 * 128 * 68 * 4 + 2 * 128 * 72 * 2
                      + 2 * 128 * 136 * 2 + 64 * 132 * 4;        // 209920
    cudaFuncSetAttribute(proj_qkv,  cudaFuncAttributeMaxDynamicSharedMemorySize, SMEMP);
    cudaFuncSetAttribute(proj_out,  cudaFuncAttributeMaxDynamicSharedMemorySize, SMEMP);
    cudaFuncSetAttribute(scores_av, cudaFuncAttributeMaxDynamicSharedMemorySize, SC_SMEM);

    const int NW4 = 1024 * 1024 / 4;        // 262144 -> 1024 blocks
    const int NE4 = 1535 * 64 / 4;          //  24560 ->   96 blocks
    const int NX4 = M_ * D_ / 4;            // 1572864 -> 6144... wait: 6144*1024/4 = 1572864 -> 6144 blocks? No: /256 = 6144.
    const int XBLK = (NX4 + 255) / 256;     // 6144 blocks (x-dim)

    // single conversion launch: z = 0..7 (idle blocks exit immediately)
    conv_all<<<dim3(XBLK, 1, 8), 256>>>(
        (const float4*)w_q, (const float4*)w_k, (const float4*)w_v,
        (const float4*)w_o, (const float4*)relE,
        (const float4*)query, (const float4*)key, (const float4*)value,
        NW4, NE4, NX4);

    proj_qkv<<<dim3(8, 48, 3), 256, SMEMP>>>(b_q, b_k, b_v, qp, kp);

    scores_av<<<dim3(6, 128), 256, SC_SMEM>>>();

    proj_out<<<dim3(8, 48), 256, SMEMP>>>(b_o, out);
}